// round 1
// baseline (speedup 1.0000x reference)
#include <cuda_runtime.h>
#include <math.h>

#define BATCH 4
#define NPTS 8192
#define NROWS (BATCH*NPTS)
#define KNN 20
#define XC_STRIDE 224

// output layout (flattened tuple concat, f32)
#define OFF_VC  0
#define OFF_NV  768
#define OFF_NVS 772
#define OFF_GF  776
#define OFF_XC  1800

// ---------------- device scratch (no allocs allowed) ----------------
__device__ float g_norms[NROWS];
__device__ int   g_idx[NROWS*KNN];
__device__ __align__(16) float g_A [(size_t)NROWS*128];
__device__ __align__(16) float g_Bn[(size_t)NROWS*128];
__device__ float g_Wa[128*64];
__device__ float g_Wb[128*64];
__device__ float g_bias[128];
__device__ float g_Wgt[224*256];   // k-major (transposed) folded global weights
__device__ float g_bgf[256];
__device__ unsigned g_enc[BATCH*256];

__device__ __forceinline__ unsigned encf(float f){
  unsigned u = __float_as_uint(f);
  return (u & 0x80000000u) ? ~u : (u | 0x80000000u);
}
__device__ __forceinline__ float decf(unsigned e){
  unsigned u = (e & 0x80000000u) ? (e ^ 0x80000000u) : ~e;
  return __uint_as_float(u);
}

// ---------------- BN fold kernels ----------------
__global__ void fold_edge_kernel(const float* __restrict__ W, const float* __restrict__ ga,
                                 const float* __restrict__ be, const float* __restrict__ mu,
                                 const float* __restrict__ va, int O, int C) {
  int i = blockIdx.x*blockDim.x + threadIdx.x;
  if (i < O*C){
    int o = i / C, c = i - o*C;
    float s = ga[o]*rsqrtf(va[o]+1e-5f);
    float wc = W[o*2*C + c];
    float wn = W[o*2*C + C + c];
    g_Wa[i] = (wc-wn)*s;
    g_Wb[i] = wn*s;
  }
  if (i < O){
    float s = ga[i]*rsqrtf(va[i]+1e-5f);
    g_bias[i] = be[i] - mu[i]*s;
  }
}

__global__ void fold_global_kernel(const float* __restrict__ Wg, const float* __restrict__ gg,
                                   const float* __restrict__ bg, const float* __restrict__ mg,
                                   const float* __restrict__ vg) {
  int i = blockIdx.x*blockDim.x + threadIdx.x;
  if (i < 224*256){
    int kk = i >> 8, o = i & 255;
    float s = gg[o]*rsqrtf(vg[o]+1e-5f);
    g_Wgt[i] = Wg[o*224+kk]*s;
  }
  if (i < 256){
    float s = gg[i]*rsqrtf(vg[i]+1e-5f);
    g_bgf[i] = bg[i] - mg[i]*s;
  }
  if (i < BATCH*256) g_enc[i] = 0u;  // encoded -inf
}

// ---------------- norms ----------------
__global__ void norms_kernel(const float* __restrict__ x, int stride, int C) {
  int i = blockIdx.x*blockDim.x + threadIdx.x;
  if (i >= NROWS) return;
  const float* p = x + (size_t)i*stride;
  float s = 0.f;
  for (int c = 0; c < C; c++){ float v = p[c]; s += v*v; }
  g_norms[i] = s;
}

// ---------------- exact kNN (top-21 incl. self, drop rank 0) ----------------
template<int C, int TS>
__global__ void __launch_bounds__(256) knn_kernel(const float* __restrict__ x, int stride) {
  __shared__ __align__(16) float s[TS*C];
  __shared__ float sn[TS];
  const int b = blockIdx.y;
  const int qi = blockIdx.x*blockDim.x + threadIdx.x;
  const size_t bbase = (size_t)b * NPTS;

  float q[C];
  #pragma unroll
  for (int c = 0; c < C; c++) q[c] = x[(bbase + qi)*stride + c];
  const float qq = g_norms[bbase + qi];

  float bd[KNN+1]; int bi[KNN+1];
  #pragma unroll
  for (int i = 0; i <= KNN; i++){ bd[i] = 3.4e38f; bi[i] = 0x7FFFFFFF; }
  float worst = 3.4e38f; int worsti = 0x7FFFFFFF;

  for (int t0 = 0; t0 < NPTS; t0 += TS) {
    __syncthreads();
    for (int i = threadIdx.x; i < TS*C; i += blockDim.x) {
      int j = i / C, c = i - j*C;
      s[i] = x[(bbase + t0 + j)*stride + c];
    }
    for (int i = threadIdx.x; i < TS; i += blockDim.x) sn[i] = g_norms[bbase + t0 + i];
    __syncthreads();

    #pragma unroll 4
    for (int j = 0; j < TS; j++) {
      float dot = 0.f;
      if (C % 4 == 0) {
        const float4* s4 = reinterpret_cast<const float4*>(s + j*C);
        #pragma unroll
        for (int c4 = 0; c4 < C/4; c4++){
          float4 v = s4[c4];
          dot += q[4*c4+0]*v.x + q[4*c4+1]*v.y + q[4*c4+2]*v.z + q[4*c4+3]*v.w;
        }
      } else {
        #pragma unroll
        for (int c = 0; c < C; c++) dot += q[c]*s[j*C+c];
      }
      float d = qq - 2.f*dot + sn[j];
      int jj = t0 + j;
      if (d < worst || (d == worst && jj < worsti)) {
        int pos = 0;
        #pragma unroll
        for (int i2 = 0; i2 <= KNN; i2++)
          pos += (bd[i2] < d || (bd[i2] == d && bi[i2] < jj)) ? 1 : 0;
        #pragma unroll
        for (int p = KNN; p >= 1; p--)
          if (p > pos) { bd[p] = bd[p-1]; bi[p] = bi[p-1]; }
        #pragma unroll
        for (int p = 0; p <= KNN; p++)
          if (p == pos) { bd[p] = d; bi[p] = jj; }
        worst = bd[KNN]; worsti = bi[KNN];
      }
    }
  }
  int* o = g_idx + (bbase + qi)*KNN;
  #pragma unroll
  for (int i = 1; i <= KNN; i++) o[i-1] = bi[i];
}

// ---------------- per-point transforms A = X*(Wc-Wn)^T + bias, Bn = X*Wn^T ----------------
template<int C, int O>
__global__ void __launch_bounds__(256) transform_kernel(const float* __restrict__ x, int stride) {
  __shared__ __align__(16) float sW[O*C];
  __shared__ float sb[O];
  const bool isA = (blockIdx.y == 0);
  const float* W = isA ? g_Wa : g_Wb;
  for (int i = threadIdx.x; i < O*C; i += 256) sW[i] = W[i];
  for (int i = threadIdx.x; i < O;   i += 256) sb[i] = isA ? g_bias[i] : 0.f;
  __syncthreads();
  int r = blockIdx.x*256 + threadIdx.x;
  float q[C];
  #pragma unroll
  for (int c = 0; c < C; c++) q[c] = x[(size_t)r*stride + c];
  float* dst = (isA ? g_A : g_Bn) + (size_t)r*O;
  #pragma unroll 4
  for (int o = 0; o < O; o++){
    float acc = sb[o];
    if (C % 4 == 0) {
      const float4* w4 = reinterpret_cast<const float4*>(sW + o*C);
      #pragma unroll
      for (int c4 = 0; c4 < C/4; c4++){
        float4 w = w4[c4];
        acc += q[4*c4+0]*w.x + q[4*c4+1]*w.y + q[4*c4+2]*w.z + q[4*c4+3]*w.w;
      }
    } else {
      #pragma unroll
      for (int c = 0; c < C; c++) acc += q[c]*sW[o*C+c];
    }
    dst[o] = acc;
  }
}

// ---------------- gather + max + leaky, write into x_concat ----------------
template<int O>
__global__ void __launch_bounds__(256) gathermax_kernel(float* __restrict__ outc) {
  const int TPP = O/4;            // threads per point (float4 lanes)
  const int PP  = 256/TPP;        // points per block
  int pl = threadIdx.x / TPP;
  int ol = threadIdx.x % TPP;
  int r  = blockIdx.x * PP + pl;  // global row
  int b  = r / NPTS;
  const int* id = g_idx + (size_t)r*KNN;
  const size_t brow = (size_t)b*NPTS;
  float4 mx = make_float4(-3.4e38f,-3.4e38f,-3.4e38f,-3.4e38f);
  #pragma unroll 5
  for (int j = 0; j < KNN; j++){
    int nb = id[j];
    const float4* Bp = reinterpret_cast<const float4*>(g_Bn + (brow + nb)*O);
    float4 v = __ldg(&Bp[ol]);
    mx.x = fmaxf(mx.x, v.x); mx.y = fmaxf(mx.y, v.y);
    mx.z = fmaxf(mx.z, v.z); mx.w = fmaxf(mx.w, v.w);
  }
  const float4* Ap = reinterpret_cast<const float4*>(g_A + (size_t)r*O);
  float4 a = Ap[ol];
  float4 y;
  y.x = a.x + mx.x; y.x = y.x >= 0.f ? y.x : 0.2f*y.x;
  y.y = a.y + mx.y; y.y = y.y >= 0.f ? y.y : 0.2f*y.y;
  y.z = a.z + mx.z; y.z = y.z >= 0.f ? y.z : 0.2f*y.z;
  y.w = a.w + mx.w; y.w = y.w >= 0.f ? y.w : 0.2f*y.w;
  *reinterpret_cast<float4*>(outc + (size_t)r*XC_STRIDE + ol*4) = y;
}

// ---------------- global conv (224 -> 256) + per-batch max ----------------
__global__ void __launch_bounds__(256) globalconv_kernel(const float* __restrict__ xc) {
  __shared__ float Xs[64][33];
  __shared__ __align__(16) float Ws[32][64];
  __shared__ unsigned smax[64];
  const int b = blockIdx.y, n0 = blockIdx.x*64, ob = blockIdx.z*64;
  const int rr = threadIdx.x >> 2, oc = threadIdx.x & 3;
  float acc[16];
  #pragma unroll
  for (int i = 0; i < 16; i++) acc[i] = g_bgf[ob + oc*16 + i];

  for (int kc = 0; kc < 224; kc += 32){
    __syncthreads();
    for (int i = threadIdx.x; i < 64*32; i += 256){
      int r2 = i >> 5, kk = i & 31;
      Xs[r2][kk] = xc[((size_t)b*NPTS + n0 + r2)*XC_STRIDE + kc + kk];
    }
    for (int i = threadIdx.x; i < 32*64; i += 256){
      int kk = i >> 6, oo = i & 63;
      Ws[kk][oo] = g_Wgt[(kc+kk)*256 + ob + oo];
    }
    __syncthreads();
    #pragma unroll
    for (int kk = 0; kk < 32; kk++){
      float xv = Xs[rr][kk];
      const float4* w4 = reinterpret_cast<const float4*>(&Ws[kk][oc*16]);
      #pragma unroll
      for (int q4 = 0; q4 < 4; q4++){
        float4 w = w4[q4];
        acc[q4*4+0] += xv*w.x; acc[q4*4+1] += xv*w.y;
        acc[q4*4+2] += xv*w.z; acc[q4*4+3] += xv*w.w;
      }
    }
  }
  if (threadIdx.x < 64) smax[threadIdx.x] = 0u;
  __syncthreads();
  #pragma unroll
  for (int i = 0; i < 16; i++){
    float y = acc[i]; y = y >= 0.f ? y : 0.2f*y;
    atomicMax(&smax[oc*16 + i], encf(y));
  }
  __syncthreads();
  if (threadIdx.x < 64) atomicMax(&g_enc[b*256 + ob + threadIdx.x], smax[threadIdx.x]);
}

// ---------------- heads ----------------
__global__ void head_kernel(const float* __restrict__ Wv1, const float* __restrict__ bv1,
                            const float* __restrict__ Wv2, const float* __restrict__ bv2,
                            const float* __restrict__ Wq1, const float* __restrict__ bq1,
                            const float* __restrict__ Wq2, const float* __restrict__ bq2,
                            float* __restrict__ out) {
  __shared__ float gf[256]; __shared__ float h[512]; __shared__ float qh[64];
  int tid = threadIdx.x;
  for (int b = 0; b < BATCH; b++){
    {
      float v = decf(g_enc[b*256 + tid]);
      gf[tid] = v;
      out[OFF_GF + b*256 + tid] = v;
    }
    __syncthreads();
    for (int o = tid; o < 512; o += 256){
      float a = bv1[o];
      for (int c = 0; c < 256; c++) a += gf[c]*Wv1[o*256+c];
      h[o] = fmaxf(a, 0.f);
    }
    if (tid < 64){
      float a = bq1[tid];
      for (int c = 0; c < 256; c++) a += gf[c]*Wq1[tid*256+c];
      qh[tid] = fmaxf(a, 0.f);
    }
    __syncthreads();
    if (tid < 192){
      float a = bv2[tid];
      for (int c = 0; c < 512; c++) a += h[c]*Wv2[tid*512+c];
      out[OFF_VC + b*192 + tid] = a;
    }
    if (tid == 0){
      float a = bq2[0];
      for (int c = 0; c < 64; c++) a += qh[c]*Wq2[c];
      float s = 1.f/(1.f + expf(-a));
      out[OFF_NVS + b] = s;
      float nv = rintf(s*64.f);
      nv = fminf(fmaxf(nv, 1.f), 64.f);
      out[OFF_NV + b] = nv;
    }
    __syncthreads();
  }
}

// ---------------- launch ----------------
extern "C" void kernel_launch(void* const* d_in, const int* in_sizes, int n_in,
                              void* d_out, int out_size) {
  const float* x   = (const float*)d_in[0];
  const float* W1  = (const float*)d_in[1];
  const float* g1  = (const float*)d_in[2];
  const float* b1  = (const float*)d_in[3];
  const float* m1  = (const float*)d_in[4];
  const float* v1  = (const float*)d_in[5];
  const float* W2  = (const float*)d_in[6];
  const float* g2  = (const float*)d_in[7];
  const float* b2  = (const float*)d_in[8];
  const float* m2  = (const float*)d_in[9];
  const float* v2  = (const float*)d_in[10];
  const float* W3  = (const float*)d_in[11];
  const float* g3  = (const float*)d_in[12];
  const float* b3  = (const float*)d_in[13];
  const float* m3  = (const float*)d_in[14];
  const float* v3  = (const float*)d_in[15];
  const float* Wg  = (const float*)d_in[16];
  const float* gg  = (const float*)d_in[17];
  const float* bg  = (const float*)d_in[18];
  const float* mg  = (const float*)d_in[19];
  const float* vg  = (const float*)d_in[20];
  const float* Wv1 = (const float*)d_in[21];
  const float* bv1 = (const float*)d_in[22];
  const float* Wv2 = (const float*)d_in[23];
  const float* bv2 = (const float*)d_in[24];
  const float* Wq1 = (const float*)d_in[25];
  const float* bq1 = (const float*)d_in[26];
  const float* Wq2 = (const float*)d_in[27];
  const float* bq2 = (const float*)d_in[28];

  float* out = (float*)d_out;
  float* xc  = out + OFF_XC;

  // ---- EdgeConv 1: 5 -> 32 (cols 0..31) ----
  fold_edge_kernel<<<(32*5+255)/256, 256>>>(W1, g1, b1, m1, v1, 32, 5);
  norms_kernel<<<NROWS/256, 256>>>(x, 5, 5);
  knn_kernel<5,128><<<dim3(NPTS/256, BATCH), 256>>>(x, 5);
  transform_kernel<5,32><<<dim3(NROWS/256, 2), 256>>>(x, 5);
  gathermax_kernel<32><<<NROWS/32, 256>>>(xc + 0);

  // ---- EdgeConv 2: 32 -> 64 (cols 32..95) ----
  fold_edge_kernel<<<(64*32+255)/256, 256>>>(W2, g2, b2, m2, v2, 64, 32);
  norms_kernel<<<NROWS/256, 256>>>(xc, XC_STRIDE, 32);
  knn_kernel<32,128><<<dim3(NPTS/256, BATCH), 256>>>(xc, XC_STRIDE);
  transform_kernel<32,64><<<dim3(NROWS/256, 2), 256>>>(xc, XC_STRIDE);
  gathermax_kernel<64><<<NROWS/16, 256>>>(xc + 32);

  // ---- EdgeConv 3: 64 -> 128 (cols 96..223) ----
  fold_edge_kernel<<<(128*64+255)/256, 256>>>(W3, g3, b3, m3, v3, 128, 64);
  norms_kernel<<<NROWS/256, 256>>>(xc + 32, XC_STRIDE, 64);
  knn_kernel<64,128><<<dim3(NPTS/256, BATCH), 256>>>(xc + 32, XC_STRIDE);
  transform_kernel<64,128><<<dim3(NROWS/256, 2), 256>>>(xc + 32, XC_STRIDE);
  gathermax_kernel<128><<<NROWS/8, 256>>>(xc + 96);

  // ---- global conv + maxpool + heads ----
  fold_global_kernel<<<224, 256>>>(Wg, gg, bg, mg, vg);
  globalconv_kernel<<<dim3(NPTS/64, BATCH, 4), 256>>>(xc);
  head_kernel<<<1, 256>>>(Wv1, bv1, Wv2, bv2, Wq1, bq1, Wq2, bq2, out);
}